// round 9
// baseline (speedup 1.0000x reference)
#include <cuda_runtime.h>
#include <cuda_bf16.h>
#include <cstdint>

#define N      4096
#define D      64
#define NB     128      // persistent blocks; 1/SM, all co-resident
#define NTHR   512      // 16 warps: tile split 4x4 ways
#define ITERS  100
#define NT     32       // 32x32 grid of 128x128 tiles
#define SA     36       // A smem row stride (uint32): bank=(4r+c)%32, conflict-free
#define SBH    20       // B half-tile row stride (uint32): bank=(20r+c)%32, conflict-free

// ---------------- device globals (no allocation allowed) --------------------------
__device__ float         g_K[(size_t)N * N];   // written only for nonzero tiles
__device__ float         g_M[(size_t)N * N];
__device__ uint32_t      g_x0h[N * 32];        // A bf16, full rows (32 uint32/row)
__device__ uint32_t      g_x1l[N * 16];        // B bf16 dims 0..31  (16 uint32/row)
__device__ uint32_t      g_x1h2[N * 16];       // B bf16 dims 32..63 (16 uint32/row)
__device__ float         g_sq0_32[N], g_sq0_64[N];
__device__ float         g_sq1_32[N], g_sq1_64[N];
__device__ float         g_u[N], g_v[N];
__device__ unsigned      g_bar_count;          // self-resets to 0 at every barrier
__device__ unsigned      g_bar_phase;          // monotone; compared relatively
__device__ int           g_changed[ITERS];
__device__ float         g_cost;
__device__ int           g_tilemap[NT * NT];
__device__ int           g_blockany[NB];       // per-block OR of its tile flags

// ---------------- cp.async helpers -------------------------------------------------
__device__ __forceinline__ void cpa16(uint32_t dst, const void* src) {
    asm volatile("cp.async.cg.shared.global [%0], [%1], 16;" :: "r"(dst), "l"(src));
}
#define CP_COMMIT() asm volatile("cp.async.commit_group;")
#define CP_WAIT0()  asm volatile("cp.async.wait_group 0;")

// ---------------- self-resetting grid barrier --------------------------------------
__device__ __forceinline__ void gsync() {
    __syncthreads();
    if (threadIdx.x == 0) {
        __threadfence();
        unsigned ph = atomicAdd(&g_bar_phase, 0u);
        if (atomicAdd(&g_bar_count, 1u) == (unsigned)NB - 1u) {
            atomicExch(&g_bar_count, 0u);
            atomicAdd(&g_bar_phase, 1u);
        } else {
            while (atomicAdd(&g_bar_phase, 0u) == ph) __nanosleep(32);
        }
        __threadfence();
    }
    __syncthreads();
}

// ---------------- mma over 2 k-steps (dims lo) from smem; 32x32 warp tile ----------
__device__ __forceinline__ void mma2(float (&acc)[2][4][4],
                                     const uint32_t* Ah, const uint32_t* Bh,
                                     int AR, int BR, int gid, int pid) {
#pragma unroll
    for (int kk = 0; kk < 2; kk++) {
        const int ac = kk * 8 + pid;
        const int bc = kk * 8 + pid;
        uint32_t a[2][4], b[4][2];
#pragma unroll
        for (int mi = 0; mi < 2; mi++) {
            int r = AR + mi * 16 + gid;
            a[mi][0] = Ah[r * SA + ac];
            a[mi][1] = Ah[(r + 8) * SA + ac];
            a[mi][2] = Ah[r * SA + ac + 4];
            a[mi][3] = Ah[(r + 8) * SA + ac + 4];
        }
#pragma unroll
        for (int ni = 0; ni < 4; ni++) {
            int c = BR + ni * 8 + gid;
            b[ni][0] = Bh[c * SBH + bc];
            b[ni][1] = Bh[c * SBH + bc + 4];
        }
#pragma unroll
        for (int mi = 0; mi < 2; mi++)
#pragma unroll
            for (int ni = 0; ni < 4; ni++)
                asm volatile(
                    "mma.sync.aligned.m16n8k16.row.col.f32.bf16.bf16.f32 "
                    "{%0,%1,%2,%3}, {%4,%5,%6,%7}, {%8,%9}, {%0,%1,%2,%3};"
                    : "+f"(acc[mi][ni][0]), "+f"(acc[mi][ni][1]),
                      "+f"(acc[mi][ni][2]), "+f"(acc[mi][ni][3])
                    : "r"(a[mi][0]), "r"(a[mi][1]), "r"(a[mi][2]), "r"(a[mi][3]),
                      "r"(b[ni][0]), "r"(b[ni][1]));
    }
}

// ---------------- rare path: hi dims, B fragments straight from global --------------
__device__ __forceinline__ void mma2g_hi(float (&acc)[2][4][4],
                                         const uint32_t* Ah, int ct,
                                         int AR, int BR, int gid, int pid) {
#pragma unroll
    for (int kk = 0; kk < 2; kk++) {
        const int ac = (2 + kk) * 8 + pid;
        const int bc = kk * 8 + pid;
        uint32_t a[2][4], b[4][2];
#pragma unroll
        for (int mi = 0; mi < 2; mi++) {
            int r = AR + mi * 16 + gid;
            a[mi][0] = Ah[r * SA + ac];
            a[mi][1] = Ah[(r + 8) * SA + ac];
            a[mi][2] = Ah[r * SA + ac + 4];
            a[mi][3] = Ah[(r + 8) * SA + ac + 4];
        }
#pragma unroll
        for (int ni = 0; ni < 4; ni++) {
            int c = ct * 128 + BR + ni * 8 + gid;
            b[ni][0] = g_x1h2[(size_t)c * 16 + bc];
            b[ni][1] = g_x1h2[(size_t)c * 16 + bc + 4];
        }
#pragma unroll
        for (int mi = 0; mi < 2; mi++)
#pragma unroll
            for (int ni = 0; ni < 4; ni++)
                asm volatile(
                    "mma.sync.aligned.m16n8k16.row.col.f32.bf16.bf16.f32 "
                    "{%0,%1,%2,%3}, {%4,%5,%6,%7}, {%8,%9}, {%0,%1,%2,%3};"
                    : "+f"(acc[mi][ni][0]), "+f"(acc[mi][ni][1]),
                      "+f"(acc[mi][ni][2]), "+f"(acc[mi][ni][3])
                    : "r"(a[mi][0]), "r"(a[mi][1]), "r"(a[mi][2]), "r"(a[mi][3]),
                      "r"(b[ni][0]), "r"(b[ni][1]));
    }
}

// =============== the whole pipeline in ONE persistent kernel =======================
__global__ void __launch_bounds__(NTHR, 1) kern_all(const float* __restrict__ x0,
                                                    const float* __restrict__ x1,
                                                    float* __restrict__ out) {
    // smem pool: Ah[4608] | B0a[2560] | B0b[2560] | sq1s[1024]  = 43 KB
    __shared__ uint32_t s_pool[10752];
    uint32_t* const Ah = s_pool;
    uint32_t* const B0[2] = { s_pool + 4608, s_pool + 7168 };
    float* const sq1s = (float*)(s_pool + 9728);   // 1024 staged sq1_32 values
    float* const sred = (float*)s_pool;            // phase-2 overlay (512 floats)

    const int tid  = threadIdx.x;
    const int bid  = blockIdx.x;
    const int lane = tid & 31;
    const int w    = tid >> 5;                // 0..15
    const int gid  = lane >> 2;
    const int pid  = lane & 3;
    const int wm   = w >> 2;                  // 0..3
    const int wn   = w & 3;                   // 0..3

    // =========== phase 0: fp32 -> bf16 (x1 split lo/hi), partial + full norms =====
    if (bid == 0) {
        if (tid == 0) g_cost = 0.0f;
        if (tid < ITERS) g_changed[tid] = 0;
    }
    {
        int g   = bid * NTHR + tid;           // 0..65535 = 8192 rows x 8 octs
        int row = g >> 3;
        int oct = g & 7;                      // 8 dims per oct
        const float* src = (row < N) ? x0 + (size_t)row * D
                                     : x1 + (size_t)(row - N) * D;
        uint32_t* dsth;
        int base;
        if (row < N) { dsth = g_x0h + (size_t)row * 32; base = oct * 4; }
        else {
            int r1 = row - N;
            if (oct < 4) { dsth = g_x1l  + (size_t)r1 * 16; base = oct * 4; }
            else         { dsth = g_x1h2 + (size_t)r1 * 16; base = (oct - 4) * 4; }
        }
        float s = 0.0f;
#pragma unroll
        for (int i = 0; i < 2; i++) {
            float4 v4 = *(const float4*)(src + oct * 8 + i * 4);
            s += v4.x * v4.x + v4.y * v4.y + v4.z * v4.z + v4.w * v4.w;
            __nv_bfloat162 p0 = __floats2bfloat162_rn(v4.x, v4.y);
            __nv_bfloat162 p1 = __floats2bfloat162_rn(v4.z, v4.w);
            dsth[base + i * 2]     = *(uint32_t*)&p0;
            dsth[base + i * 2 + 1] = *(uint32_t*)&p1;
        }
        // lanes: 8 consecutive octs per row (oct == lane&7)
        float s1 = s  + __shfl_xor_sync(0xffffffffu, s,  1);
        s1 += __shfl_xor_sync(0xffffffffu, s1, 2);             // 32-dim half sum
        float s2 = s1 + __shfl_xor_sync(0xffffffffu, s1, 4);   // full row
        if (oct == 0) {
            if (row < N) { g_sq0_32[row] = s1; g_sq0_64[row] = s2; }
            else         { g_sq1_32[row - N] = s1; g_sq1_64[row - N] = s2; }
        }
    }
    gsync();

    // =========== phase 1: screened GEMM, 8 tiles per block ========================
    {
        const int rs = bid >> 2;              // row slab 0..31 (A reused 8x)
        const int cg = bid & 3;               // col group: tiles cg*8 .. cg*8+7
        const uint32_t sb = (uint32_t)__cvta_generic_to_shared(s_pool);
        const uint32_t offB0[2] = { 4608u * 4u, 7168u * 4u };

        // stage sq1_32 for this block's 1024 columns into smem (coalesced)
#pragma unroll
        for (int i = 0; i < 2; i++)
            sq1s[tid + i * NTHR] = g_sq1_32[cg * 1024 + tid + i * NTHR];

        // A slab (full 64 dims): 1024 uint4, 2/thread
        {
            const uint4* GA = (const uint4*)(g_x0h + (size_t)rs * 128 * 32);
#pragma unroll
            for (int i = 0; i < 2; i++) {
                int f = tid + i * NTHR; int r = f >> 3; int c4 = f & 7;
                cpa16(sb + (uint32_t)(r * SA + c4 * 4) * 4u, GA + r * 8 + c4);
            }
        }
        // B half-tile loader: contiguous 8 KB block of g_x1l; 512 uint4, 1/thread
        auto loadBlo = [&](uint32_t off, int ct) {
            const uint4* GB = (const uint4*)g_x1l + (size_t)ct * 512;
            int r = tid >> 2; int c4 = tid & 3;
            cpa16(sb + off + (uint32_t)(r * SBH + c4 * 4) * 4u, GB + tid);
        };
        loadBlo(offB0[0], cg * 8);
        CP_COMMIT();

        // hoist sq0 for this warp's 32 rows into registers
        const int gr = rs * 128 + wm * 32;
        float r032[2][2], r064[2][2];
#pragma unroll
        for (int mi = 0; mi < 2; mi++) {
            r032[mi][0] = g_sq0_32[gr + mi * 16 + gid];
            r032[mi][1] = g_sq0_32[gr + mi * 16 + gid + 8];
            r064[mi][0] = g_sq0_64[gr + mi * 16 + gid];
            r064[mi][1] = g_sq0_64[gr + mi * 16 + gid + 8];
        }

        const int AR = wm * 32, BR = wn * 32;
        int blkany = 0;
        int cur = 0;
        for (int k = 0; k < 8; k++) {
            const int ct = cg * 8 + k;
            CP_WAIT0(); __syncthreads();

            // prefetch k+1 FIRST: buffer cur^1 is free, latency hides behind mma
            if (k < 7) { loadBlo(offB0[cur ^ 1], ct + 1); CP_COMMIT(); }

            float acc[2][4][4];
#pragma unroll
            for (int mi = 0; mi < 2; mi++)
#pragma unroll
                for (int ni = 0; ni < 4; ni++)
#pragma unroll
                    for (int f = 0; f < 4; f++) acc[mi][ni][f] = 0.0f;

            mma2(acc, Ah, B0[cur], AR, BR, gid, pid);          // dims 0..31

            // ---- exact screen: partial M (dims 0..31) is a lower bound on M ----
            const int lc0 = k * 128 + wn * 32;                 // col within group
            int need = 0;
#pragma unroll
            for (int mi = 0; mi < 2; mi++)
#pragma unroll
                for (int ni = 0; ni < 4; ni++) {
                    int c = lc0 + ni * 8 + 2 * pid;
                    float s1a = sq1s[c], s1b = sq1s[c + 1];
                    float m0 = fmaf(-2.0f, acc[mi][ni][0], r032[mi][0] + s1a);
                    float m1 = fmaf(-2.0f, acc[mi][ni][1], r032[mi][0] + s1b);
                    float m2 = fmaf(-2.0f, acc[mi][ni][2], r032[mi][1] + s1a);
                    float m3 = fmaf(-2.0f, acc[mi][ni][3], r032[mi][1] + s1b);
                    need |= (fminf(fminf(m0, m1), fminf(m2, m3)) < 11.0f) ? 1 : 0;
                }
            int mapv = 0;
            if (__syncthreads_or(need)) {
                // rare: finish dims 32..63 exactly (B frags direct from global)
                mma2g_hi(acc, Ah, ct, AR, BR, gid, pid);
                const int gc = ct * 128 + wn * 32;
                int need2 = 0;
#pragma unroll
                for (int mi = 0; mi < 2; mi++)
#pragma unroll
                    for (int ni = 0; ni < 4; ni++) {
                        int c = gc + ni * 8 + 2 * pid;
                        float s1a = g_sq1_64[c], s1b = g_sq1_64[c + 1];
                        float m0 = fmaxf(fmaf(-2.0f, acc[mi][ni][0], r064[mi][0] + s1a), 0.0f);
                        float m1 = fmaxf(fmaf(-2.0f, acc[mi][ni][1], r064[mi][0] + s1b), 0.0f);
                        float m2 = fmaxf(fmaf(-2.0f, acc[mi][ni][2], r064[mi][1] + s1a), 0.0f);
                        float m3 = fmaxf(fmaf(-2.0f, acc[mi][ni][3], r064[mi][1] + s1b), 0.0f);
                        need2 |= (fminf(fminf(m0, m1), fminf(m2, m3)) < 11.0f) ? 1 : 0;
                        int r0 = gr + mi * 16 + gid;
                        *(float2*)(g_M + (size_t)r0 * N + c)       = make_float2(m0, m1);
                        *(float2*)(g_M + (size_t)(r0 + 8) * N + c) = make_float2(m2, m3);
                        *(float2*)(g_K + (size_t)r0 * N + c)       =
                            make_float2(expf(-10.0f * m0), expf(-10.0f * m1));
                        *(float2*)(g_K + (size_t)(r0 + 8) * N + c) =
                            make_float2(expf(-10.0f * m2), expf(-10.0f * m3));
                    }
                mapv = __syncthreads_or(need2);
            }
            if (tid == 0) g_tilemap[rs * NT + ct] = mapv;
            blkany |= mapv;
            cur ^= 1;
        }
        if (tid == 0) g_blockany[bid] = blkany;
    }
    gsync();

    // =========== phase 2: Sinkhorn (or exact zero fast path) ======================
    {
        int loc = (tid < NB) ? g_blockany[tid] : 0;
        if (!__syncthreads_or(loc)) {
            if (bid == 0 && tid == 0) out[0] = 0.0f;   // P == 0 exactly -> cost == 0
            return;                                     // uniform across all blocks
        }
    }

    const float AB    = 1.0f / (float)N;
    const float DELTA = 1e-8f;
    {
        int gi = bid * NTHR + tid;
        if (gi < N) { g_u[gi] = 1.0f; g_v[gi] = 1.0f; }
    }
    gsync();

    for (int it = 0; it < ITERS; it++) {
        // u-pass: warp-per-row (2 rows/warp), skip all-zero tiles
#pragma unroll
        for (int rr = 0; rr < 2; rr++) {
            int r  = bid * 32 + w * 2 + rr;
            int rt = r >> 7;
            const int* map = g_tilemap + rt * NT;
            const float4* kr = (const float4*)(g_K + (size_t)r * N);
            const float4* vv = (const float4*)g_v;
            float s = 0.0f;
            for (int ct = 0; ct < NT; ct++) {
                if (!map[ct]) continue;
                int j = ct * 32 + lane;
                float4 kq = kr[j];
                float4 vq = vv[j];
                s += kq.x * vq.x + kq.y * vq.y + kq.z * vq.z + kq.w * vq.w;
            }
#pragma unroll
            for (int o = 16; o; o >>= 1) s += __shfl_xor_sync(0xffffffffu, s, o);
            if (lane == 0) {
                float un = AB / (s + DELTA);
                if (un != g_u[r]) g_changed[it] = 1;
                g_u[r] = un;
            }
        }
        gsync();

        // v-pass: 32-col stripe per block (16-row stride), skip all-zero tiles
        {
            int c  = bid * 32 + lane;
            int ct = bid >> 2;
            float s = 0.0f;
            for (int rt = 0; rt < NT; rt++) {
                if (!g_tilemap[rt * NT + ct]) continue;
                int rbase = rt * 128;
#pragma unroll 4
                for (int r = rbase + w; r < rbase + 128; r += 16)
                    s += g_K[(size_t)r * N + c] * g_u[r];
            }
            sred[tid] = s;
            __syncthreads();
            if (tid < 32) {
                float t = sred[tid];
#pragma unroll
                for (int g = 1; g < 16; g++) t += sred[tid + g * 32];
                float vn = AB / (t + DELTA);
                if (vn != g_v[c]) g_changed[it] = 1;
                g_v[c] = vn;
            }
        }
        gsync();

        if (g_changed[it] == 0) break;    // exact bitwise fixed point (uniform)
    }

    // cost = sum_ij u_i * K_ij * v_j * M_ij (zero tiles contribute exactly 0)
    {
        float wsum = 0.0f;
#pragma unroll
        for (int rr = 0; rr < 2; rr++) {
            int r  = bid * 32 + w * 2 + rr;
            int rt = r >> 7;
            const int* map = g_tilemap + rt * NT;
            const float4* kr = (const float4*)(g_K + (size_t)r * N);
            const float4* mr = (const float4*)(g_M + (size_t)r * N);
            const float4* vv = (const float4*)g_v;
            float s = 0.0f;
            for (int ct = 0; ct < NT; ct++) {
                if (!map[ct]) continue;
                int j = ct * 32 + lane;
                float4 kq = kr[j];
                float4 mq = mr[j];
                float4 vq = vv[j];
                s += kq.x * mq.x * vq.x + kq.y * mq.y * vq.y
                   + kq.z * mq.z * vq.z + kq.w * mq.w * vq.w;
            }
#pragma unroll
            for (int o = 16; o; o >>= 1) s += __shfl_xor_sync(0xffffffffu, s, o);
            if (lane == 0) wsum += s * g_u[r];
        }
        if (lane == 0) atomicAdd(&g_cost, wsum);
    }
    gsync();
    if (bid == 0 && tid == 0) out[0] = g_cost;
}

// ---------------- launch: ONE kernel ----------------------------------------------
extern "C" void kernel_launch(void* const* d_in, const int* in_sizes, int n_in,
                              void* d_out, int out_size) {
    const float* x0 = (const float*)d_in[0];
    const float* x1 = (const float*)d_in[1];
    float* out = (float*)d_out;
    kern_all<<<NB, NTHR>>>(x0, x1, out);
}

// round 10
// speedup vs baseline: 1.0139x; 1.0139x over previous
#include <cuda_runtime.h>
#include <cuda_bf16.h>
#include <cstdint>

#define N      4096
#define D      64
#define NB     128      // persistent blocks; 1/SM, all co-resident
#define NTHR   512      // 16 warps = 2 independent groups of 8
#define ITERS  100
#define NT     32       // 32 row-slabs
#define NHT    64       // 64 column half-tiles (64 cols each)
#define SA     36       // A smem row stride (uint32), conflict-free
#define SBH    20       // B half-tile row stride (uint32), conflict-free

// ---------------- device globals (no allocation allowed) --------------------------
__device__ float         g_K[(size_t)N * N];   // written only for nonzero half-tiles
__device__ float         g_M[(size_t)N * N];
__device__ uint32_t      g_x0h[N * 32];        // A bf16, full rows (32 uint32/row)
__device__ uint32_t      g_x1l[N * 16];        // B bf16 dims 0..31  (16 uint32/row)
__device__ uint32_t      g_x1h2[N * 16];       // B bf16 dims 32..63 (16 uint32/row)
__device__ float         g_sq0_32[N], g_sq0_64[N];
__device__ float         g_sq1_32[N], g_sq1_64[N];
__device__ float         g_u[N], g_v[N];
__device__ unsigned      g_bar_count;
__device__ unsigned      g_bar_phase;
__device__ int           g_changed[ITERS];
__device__ float         g_cost;
__device__ int           g_map2[NT * NHT];     // per 128x64 half-tile flag
__device__ int           g_blockany[NB];

// ---------------- cp.async helpers -------------------------------------------------
__device__ __forceinline__ void cpa16(uint32_t dst, const void* src) {
    asm volatile("cp.async.cg.shared.global [%0], [%1], 16;" :: "r"(dst), "l"(src));
}
#define CP_COMMIT() asm volatile("cp.async.commit_group;")
#define CP_WAIT0()  asm volatile("cp.async.wait_group 0;")
#define GRP_BAR(g)  asm volatile("bar.sync %0, %1;" :: "r"((g) + 1), "r"(256) : "memory")

// ---------------- self-resetting grid barrier --------------------------------------
__device__ __forceinline__ void gsync() {
    __syncthreads();
    if (threadIdx.x == 0) {
        __threadfence();
        unsigned ph = atomicAdd(&g_bar_phase, 0u);
        if (atomicAdd(&g_bar_count, 1u) == (unsigned)NB - 1u) {
            atomicExch(&g_bar_count, 0u);
            atomicAdd(&g_bar_phase, 1u);
        } else {
            while (atomicAdd(&g_bar_phase, 0u) == ph) __nanosleep(32);
        }
        __threadfence();
    }
    __syncthreads();
}

// ---------------- mma over dims 0..31 from smem; warp = 32x32 ----------------------
__device__ __forceinline__ void mma2(float (&acc)[2][4][4],
                                     const uint32_t* Ah, const uint32_t* Bh,
                                     int AR, int BR, int gid, int pid) {
#pragma unroll
    for (int kk = 0; kk < 2; kk++) {
        const int ac = kk * 8 + pid;
        const int bc = kk * 8 + pid;
        uint32_t a[2][4], b[4][2];
#pragma unroll
        for (int mi = 0; mi < 2; mi++) {
            int r = AR + mi * 16 + gid;
            a[mi][0] = Ah[r * SA + ac];
            a[mi][1] = Ah[(r + 8) * SA + ac];
            a[mi][2] = Ah[r * SA + ac + 4];
            a[mi][3] = Ah[(r + 8) * SA + ac + 4];
        }
#pragma unroll
        for (int ni = 0; ni < 4; ni++) {
            int c = BR + ni * 8 + gid;
            b[ni][0] = Bh[c * SBH + bc];
            b[ni][1] = Bh[c * SBH + bc + 4];
        }
#pragma unroll
        for (int mi = 0; mi < 2; mi++)
#pragma unroll
            for (int ni = 0; ni < 4; ni++)
                asm volatile(
                    "mma.sync.aligned.m16n8k16.row.col.f32.bf16.bf16.f32 "
                    "{%0,%1,%2,%3}, {%4,%5,%6,%7}, {%8,%9}, {%0,%1,%2,%3};"
                    : "+f"(acc[mi][ni][0]), "+f"(acc[mi][ni][1]),
                      "+f"(acc[mi][ni][2]), "+f"(acc[mi][ni][3])
                    : "r"(a[mi][0]), "r"(a[mi][1]), "r"(a[mi][2]), "r"(a[mi][3]),
                      "r"(b[ni][0]), "r"(b[ni][1]));
    }
}

// ---------------- rare path: dims 32..63, B fragments from global -------------------
__device__ __forceinline__ void mma2g_hi(float (&acc)[2][4][4],
                                         const uint32_t* Ah, int cbase,
                                         int AR, int gid, int pid) {
#pragma unroll
    for (int kk = 0; kk < 2; kk++) {
        const int ac = (2 + kk) * 8 + pid;
        const int bc = kk * 8 + pid;
        uint32_t a[2][4], b[4][2];
#pragma unroll
        for (int mi = 0; mi < 2; mi++) {
            int r = AR + mi * 16 + gid;
            a[mi][0] = Ah[r * SA + ac];
            a[mi][1] = Ah[(r + 8) * SA + ac];
            a[mi][2] = Ah[r * SA + ac + 4];
            a[mi][3] = Ah[(r + 8) * SA + ac + 4];
        }
#pragma unroll
        for (int ni = 0; ni < 4; ni++) {
            int c = cbase + ni * 8 + gid;
            b[ni][0] = g_x1h2[(size_t)c * 16 + bc];
            b[ni][1] = g_x1h2[(size_t)c * 16 + bc + 4];
        }
#pragma unroll
        for (int mi = 0; mi < 2; mi++)
#pragma unroll
            for (int ni = 0; ni < 4; ni++)
                asm volatile(
                    "mma.sync.aligned.m16n8k16.row.col.f32.bf16.bf16.f32 "
                    "{%0,%1,%2,%3}, {%4,%5,%6,%7}, {%8,%9}, {%0,%1,%2,%3};"
                    : "+f"(acc[mi][ni][0]), "+f"(acc[mi][ni][1]),
                      "+f"(acc[mi][ni][2]), "+f"(acc[mi][ni][3])
                    : "r"(a[mi][0]), "r"(a[mi][1]), "r"(a[mi][2]), "r"(a[mi][3]),
                      "r"(b[ni][0]), "r"(b[ni][1]));
    }
}

// =============== the whole pipeline in ONE persistent kernel =======================
__global__ void __launch_bounds__(NTHR, 1) kern_all(const float* __restrict__ x0,
                                                    const float* __restrict__ x1,
                                                    float* __restrict__ out) {
    // pool: Ah[4608] | B 4x1280 | sq1s[1024] | flags[32]  = 43136 B
    __shared__ uint32_t s_pool[10784];
    uint32_t* const Ah = s_pool;
    uint32_t* const Bbuf = s_pool + 4608;            // [grp*2+buf]*1280
    float* const sq1s = (float*)(s_pool + 9728);     // 1024 staged sq1_32
    int* const flags = (int*)(s_pool + 10752);       // [0..15]=need, [16]=any
    float* const sred = (float*)s_pool;              // phase-2 overlay

    const int tid  = threadIdx.x;
    const int bid  = blockIdx.x;
    const int lane = tid & 31;
    const int w    = tid >> 5;                // 0..15
    const int gid  = lane >> 2;
    const int pid  = lane & 3;
    const int grp  = w >> 3;                  // 0,1
    const int gw   = w & 7;                   // warp in group
    const int wm   = gw >> 1;                 // 0..3 (32-row strips)
    const int wn2  = gw & 1;                  // 0..1 (32-col strips in 64)

    // =========== phase 0: fp32 -> bf16 (x1 split lo/hi), partial + full norms =====
    if (bid == 0) {
        if (tid == 0) g_cost = 0.0f;
        if (tid < ITERS) g_changed[tid] = 0;
    }
    if (tid < 32) flags[tid] = 0;
    {
        int g   = bid * NTHR + tid;           // 8192 rows x 8 octs
        int row = g >> 3;
        int oct = g & 7;
        const float* src = (row < N) ? x0 + (size_t)row * D
                                     : x1 + (size_t)(row - N) * D;
        uint32_t* dsth;
        int base;
        if (row < N) { dsth = g_x0h + (size_t)row * 32; base = oct * 4; }
        else {
            int r1 = row - N;
            if (oct < 4) { dsth = g_x1l  + (size_t)r1 * 16; base = oct * 4; }
            else         { dsth = g_x1h2 + (size_t)r1 * 16; base = (oct - 4) * 4; }
        }
        float s = 0.0f;
#pragma unroll
        for (int i = 0; i < 2; i++) {
            float4 v4 = *(const float4*)(src + oct * 8 + i * 4);
            s += v4.x * v4.x + v4.y * v4.y + v4.z * v4.z + v4.w * v4.w;
            __nv_bfloat162 p0 = __floats2bfloat162_rn(v4.x, v4.y);
            __nv_bfloat162 p1 = __floats2bfloat162_rn(v4.z, v4.w);
            dsth[base + i * 2]     = *(uint32_t*)&p0;
            dsth[base + i * 2 + 1] = *(uint32_t*)&p1;
        }
        float s1 = s  + __shfl_xor_sync(0xffffffffu, s,  1);
        s1 += __shfl_xor_sync(0xffffffffu, s1, 2);
        float s2 = s1 + __shfl_xor_sync(0xffffffffu, s1, 4);
        if (oct == 0) {
            if (row < N) { g_sq0_32[row] = s1; g_sq0_64[row] = s2; }
            else         { g_sq1_32[row - N] = s1; g_sq1_64[row - N] = s2; }
        }
    }
    gsync();

    // =========== phase 1: two independent 8-warp groups, 8 half-tiles each ========
    {
        const int rs = bid >> 2;
        const int cg = bid & 3;
        const uint32_t sb = (uint32_t)__cvta_generic_to_shared(s_pool);

#pragma unroll
        for (int i = 0; i < 2; i++)
            sq1s[tid + i * NTHR] = g_sq1_32[cg * 1024 + tid + i * NTHR];

        // A slab: 1024 uint4, 2/thread
        {
            const uint4* GA = (const uint4*)(g_x0h + (size_t)rs * 128 * 32);
#pragma unroll
            for (int i = 0; i < 2; i++) {
                int f = tid + i * NTHR; int r = f >> 3; int c4 = f & 7;
                cpa16(sb + (uint32_t)(r * SA + c4 * 4) * 4u, GA + r * 8 + c4);
            }
        }
        // B half-tile loader (group-local): 64 rows x 4 uint4 = 256, 1/thread
        const int gtid = tid & 255;
        auto loadB = [&](int buf, int ct) {
            int r = gtid >> 2; int c4 = gtid & 3;
            int row = ct * 128 + grp * 64 + r;
            cpa16(sb + 18432u + (uint32_t)(grp * 2 + buf) * 5120u
                     + (uint32_t)(r * SBH + c4 * 4) * 4u,
                  (const uint4*)g_x1l + (size_t)row * 4 + c4);
        };
        loadB(0, cg * 8);
        CP_COMMIT();
        CP_WAIT0();
        __syncthreads();          // A + first B visible to everyone; flags zeroed

        const int gr = rs * 128 + wm * 32;
        float r032[2][2], r064[2][2];
#pragma unroll
        for (int mi = 0; mi < 2; mi++) {
            r032[mi][0] = g_sq0_32[gr + mi * 16 + gid];
            r032[mi][1] = g_sq0_32[gr + mi * 16 + gid + 8];
            r064[mi][0] = g_sq0_64[gr + mi * 16 + gid];
            r064[mi][1] = g_sq0_64[gr + mi * 16 + gid + 8];
        }

        const int AR = wm * 32, BR = wn2 * 32;
        int cur = 0;
        int grpany = 0;
        for (int k = 0; k < 8; k++) {
            const int ct = cg * 8 + k;
            if (k > 0) { CP_WAIT0(); GRP_BAR(grp); }   // B_k ready (group-local)
            if (k < 7) { loadB(cur ^ 1, ct + 1); CP_COMMIT(); }

            const uint32_t* Bh = Bbuf + (grp * 2 + cur) * 1280;
            float acc[2][4][4];
#pragma unroll
            for (int mi = 0; mi < 2; mi++)
#pragma unroll
                for (int ni = 0; ni < 4; ni++)
#pragma unroll
                    for (int f = 0; f < 4; f++) acc[mi][ni][f] = 0.0f;

            mma2(acc, Ah, Bh, AR, BR, gid, pid);       // dims 0..31

            // exact screen: partial M (dims 0..31) lower-bounds M
            const int lc0 = k * 128 + grp * 64 + wn2 * 32;
            int need = 0;
#pragma unroll
            for (int mi = 0; mi < 2; mi++)
#pragma unroll
                for (int ni = 0; ni < 4; ni++) {
                    int c = lc0 + ni * 8 + 2 * pid;
                    float s1a = sq1s[c], s1b = sq1s[c + 1];
                    float m0 = fmaf(-2.0f, acc[mi][ni][0], r032[mi][0] + s1a);
                    float m1 = fmaf(-2.0f, acc[mi][ni][1], r032[mi][0] + s1b);
                    float m2 = fmaf(-2.0f, acc[mi][ni][2], r032[mi][1] + s1a);
                    float m3 = fmaf(-2.0f, acc[mi][ni][3], r032[mi][1] + s1b);
                    need |= (fminf(fminf(m0, m1), fminf(m2, m3)) < 11.0f) ? 1 : 0;
                }
            need = __ballot_sync(0xffffffffu, need) ? 1 : 0;
            if (need && lane == 0) flags[grp * 8 + k] = 1;   // benign race (all 1)
            GRP_BAR(grp);
            int mapv = flags[grp * 8 + k];

            if (mapv) {
                // rare: finish dims 32..63 exactly (B frags direct from global)
                const int gc = ct * 128 + grp * 64 + wn2 * 32;
                mma2g_hi(acc, Ah, gc, AR, gid, pid);
                int need2 = 0;
#pragma unroll
                for (int mi = 0; mi < 2; mi++)
#pragma unroll
                    for (int ni = 0; ni < 4; ni++) {
                        int c = gc + ni * 8 + 2 * pid;
                        float s1a = g_sq1_64[c], s1b = g_sq1_64[c + 1];
                        float m0 = fmaxf(fmaf(-2.0f, acc[mi][ni][0], r064[mi][0] + s1a), 0.0f);
                        float m1 = fmaxf(fmaf(-2.0f, acc[mi][ni][1], r064[mi][0] + s1b), 0.0f);
                        float m2 = fmaxf(fmaf(-2.0f, acc[mi][ni][2], r064[mi][1] + s1a), 0.0f);
                        float m3 = fmaxf(fmaf(-2.0f, acc[mi][ni][3], r064[mi][1] + s1b), 0.0f);
                        need2 |= (fminf(fminf(m0, m1), fminf(m2, m3)) < 11.0f) ? 1 : 0;
                        int r0 = gr + mi * 16 + gid;
                        *(float2*)(g_M + (size_t)r0 * N + c)       = make_float2(m0, m1);
                        *(float2*)(g_M + (size_t)(r0 + 8) * N + c) = make_float2(m2, m3);
                        *(float2*)(g_K + (size_t)r0 * N + c)       =
                            make_float2(expf(-10.0f * m0), expf(-10.0f * m1));
                        *(float2*)(g_K + (size_t)(r0 + 8) * N + c) =
                            make_float2(expf(-10.0f * m2), expf(-10.0f * m3));
                    }
                (void)need2;
                grpany = 1;
            }
            if (gw == 0 && lane == 0)
                g_map2[rs * NHT + ct * 2 + grp] = mapv;
            cur ^= 1;
        }
        if (lane == 0 && gw == 0 && grpany) flags[16] = 1;
    }
    __syncthreads();
    if (tid == 0) g_blockany[bid] = flags[16];
    gsync();

    // =========== phase 2: Sinkhorn (or exact zero fast path) ======================
    {
        int loc = (tid < NB) ? g_blockany[tid] : 0;
        if (!__syncthreads_or(loc)) {
            if (bid == 0 && tid == 0) out[0] = 0.0f;   // P == 0 exactly
            return;                                     // uniform across blocks
        }
    }

    const float AB    = 1.0f / (float)N;
    const float DELTA = 1e-8f;
    {
        int gi = bid * NTHR + tid;
        if (gi < N) { g_u[gi] = 1.0f; g_v[gi] = 1.0f; }
    }
    gsync();

    for (int it = 0; it < ITERS; it++) {
        // u-pass: 2 rows/warp, skip all-zero half-tiles (64 cols each)
#pragma unroll
        for (int rr = 0; rr < 2; rr++) {
            int r  = bid * 32 + w * 2 + rr;
            int rt = r >> 7;
            const int* map = g_map2 + rt * NHT;
            const float4* kr = (const float4*)(g_K + (size_t)r * N);
            const float4* vv = (const float4*)g_v;
            float s = 0.0f;
            for (int hct = 0; hct < NHT; hct++) {
                if (!map[hct]) continue;
                if (lane < 16) {
                    int j = hct * 16 + lane;
                    float4 kq = kr[j];
                    float4 vq = vv[j];
                    s += kq.x * vq.x + kq.y * vq.y + kq.z * vq.z + kq.w * vq.w;
                }
            }
#pragma unroll
            for (int o = 16; o; o >>= 1) s += __shfl_xor_sync(0xffffffffu, s, o);
            if (lane == 0) {
                float un = AB / (s + DELTA);
                if (un != g_u[r]) g_changed[it] = 1;
                g_u[r] = un;
            }
        }
        gsync();

        // v-pass: 32-col stripe per block; the stripe lies in half-tile bid>>1
        {
            int c   = bid * 32 + lane;
            int hct = bid >> 1;
            float s = 0.0f;
            for (int rt = 0; rt < NT; rt++) {
                if (!g_map2[rt * NHT + hct]) continue;
                int rbase = rt * 128;
#pragma unroll 4
                for (int r = rbase + w; r < rbase + 128; r += 16)
                    s += g_K[(size_t)r * N + c] * g_u[r];
            }
            sred[tid] = s;
            __syncthreads();
            if (tid < 32) {
                float t = sred[tid];
#pragma unroll
                for (int g = 1; g < 16; g++) t += sred[tid + g * 32];
                float vn = AB / (t + DELTA);
                if (vn != g_v[c]) g_changed[it] = 1;
                g_v[c] = vn;
            }
        }
        gsync();

        if (g_changed[it] == 0) break;    // exact bitwise fixed point
    }

    // cost = sum_ij u_i * K_ij * v_j * M_ij (zero half-tiles contribute 0)
    {
        float wsum = 0.0f;
#pragma unroll
        for (int rr = 0; rr < 2; rr++) {
            int r  = bid * 32 + w * 2 + rr;
            int rt = r >> 7;
            const int* map = g_map2 + rt * NHT;
            const float4* kr = (const float4*)(g_K + (size_t)r * N);
            const float4* mr = (const float4*)(g_M + (size_t)r * N);
            const float4* vv = (const float4*)g_v;
            float s = 0.0f;
            for (int hct = 0; hct < NHT; hct++) {
                if (!map[hct]) continue;
                if (lane < 16) {
                    int j = hct * 16 + lane;
                    float4 kq = kr[j];
                    float4 mq = mr[j];
                    float4 vq = vv[j];
                    s += kq.x * mq.x * vq.x + kq.y * mq.y * vq.y
                       + kq.z * mq.z * vq.z + kq.w * mq.w * vq.w;
                }
            }
#pragma unroll
            for (int o = 16; o; o >>= 1) s += __shfl_xor_sync(0xffffffffu, s, o);
            if (lane == 0) wsum += s * g_u[r];
        }
        if (lane == 0) atomicAdd(&g_cost, wsum);
    }
    gsync();
    if (bid == 0 && tid == 0) out[0] = g_cost;
}

// ---------------- launch: ONE kernel ----------------------------------------------
extern "C" void kernel_launch(void* const* d_in, const int* in_sizes, int n_in,
                              void* d_out, int out_size) {
    const float* x0 = (const float*)d_in[0];
    const float* x1 = (const float*)d_in[1];
    float* out = (float*)d_out;
    kern_all<<<NB, NTHR>>>(x0, x1, out);
}

// round 13
// speedup vs baseline: 1.0174x; 1.0035x over previous
#include <cuda_runtime.h>
#include <cuda_bf16.h>
#include <cstdint>

#define N      4096
#define D      64
#define NB     256      // 2 persistent blocks per SM, all co-resident
#define NTHR   256      // 8 warps
#define ITERS  100
#define NT     32       // 32 row-slabs
#define NHT    64       // 64 column half-tiles (64 cols each)
#define SA     36       // A smem row stride (uint32), conflict-free
#define SBH    20       // B half-tile row stride (uint32), conflict-free

// ---------------- device globals (no allocation allowed) --------------------------
__device__ float         g_K[(size_t)N * N];   // written only for flagged half-tiles
__device__ float         g_M[(size_t)N * N];
__device__ uint32_t      g_x0h[N * 32];        // A bf16, full rows (32 uint32/row)
__device__ uint32_t      g_x1l[N * 16];        // B bf16 dims 0..31  (16 uint32/row)
__device__ uint32_t      g_x1h2[N * 16];       // B bf16 dims 32..63 (16 uint32/row)
__device__ float         g_sq0_32[N], g_sq0_64[N];
__device__ float         g_sq1_32[N], g_sq1_64[N];
__device__ float         g_u[N], g_v[N];
__device__ unsigned      g_bar_count;
__device__ unsigned      g_bar_phase;
__device__ int           g_changed[ITERS];
__device__ float         g_cost;
__device__ int           g_map2[NT * NHT];     // per 128x64 half-tile flag
__device__ int           g_blockany[NB];

// ---------------- cp.async helpers -------------------------------------------------
__device__ __forceinline__ void cpa16(uint32_t dst, const void* src) {
    asm volatile("cp.async.cg.shared.global [%0], [%1], 16;" :: "r"(dst), "l"(src));
}
#define CP_COMMIT() asm volatile("cp.async.commit_group;")
#define CP_WAIT0()  asm volatile("cp.async.wait_group 0;")

// ---------------- self-resetting grid barrier --------------------------------------
__device__ __forceinline__ void gsync() {
    __syncthreads();
    if (threadIdx.x == 0) {
        __threadfence();
        unsigned ph = atomicAdd(&g_bar_phase, 0u);
        if (atomicAdd(&g_bar_count, 1u) == (unsigned)NB - 1u) {
            atomicExch(&g_bar_count, 0u);
            atomicAdd(&g_bar_phase, 1u);
        } else {
            while (atomicAdd(&g_bar_phase, 0u) == ph) __nanosleep(32);
        }
        __threadfence();
    }
    __syncthreads();
}

// ---------------- mma, dims 0..31, B in smem; warp = 32x32 -------------------------
__device__ __forceinline__ void mma_lo_s(float (&acc)[2][4][4],
                                         const uint32_t* Ah, const uint32_t* Bh,
                                         int AR, int BR, int gid, int pid) {
#pragma unroll
    for (int kk = 0; kk < 2; kk++) {
        const int ac = kk * 8 + pid;
        const int bc = kk * 8 + pid;
        uint32_t a[2][4], b[4][2];
#pragma unroll
        for (int mi = 0; mi < 2; mi++) {
            int r = AR + mi * 16 + gid;
            a[mi][0] = Ah[r * SA + ac];
            a[mi][1] = Ah[(r + 8) * SA + ac];
            a[mi][2] = Ah[r * SA + ac + 4];
            a[mi][3] = Ah[(r + 8) * SA + ac + 4];
        }
#pragma unroll
        for (int ni = 0; ni < 4; ni++) {
            int c = BR + ni * 8 + gid;
            b[ni][0] = Bh[c * SBH + bc];
            b[ni][1] = Bh[c * SBH + bc + 4];
        }
#pragma unroll
        for (int mi = 0; mi < 2; mi++)
#pragma unroll
            for (int ni = 0; ni < 4; ni++)
                asm volatile(
                    "mma.sync.aligned.m16n8k16.row.col.f32.bf16.bf16.f32 "
                    "{%0,%1,%2,%3}, {%4,%5,%6,%7}, {%8,%9}, {%0,%1,%2,%3};"
                    : "+f"(acc[mi][ni][0]), "+f"(acc[mi][ni][1]),
                      "+f"(acc[mi][ni][2]), "+f"(acc[mi][ni][3])
                    : "r"(a[mi][0]), "r"(a[mi][1]), "r"(a[mi][2]), "r"(a[mi][3]),
                      "r"(b[ni][0]), "r"(b[ni][1]));
    }
}

// ---------------- cold path: full 64-dim acc, B fragments from global ---------------
__device__ __forceinline__ void mma_full_g(float (&acc)[2][4][4],
                                           const uint32_t* Ah, int cbase,
                                           int AR, int gid, int pid) {
#pragma unroll
    for (int ks = 0; ks < 4; ks++) {
        const int ac = ks * 8 + pid;
        const int bc = (ks & 1) * 8 + pid;
        const uint32_t* Bg = (ks < 2) ? g_x1l : g_x1h2;
        uint32_t a[2][4], b[4][2];
#pragma unroll
        for (int mi = 0; mi < 2; mi++) {
            int r = AR + mi * 16 + gid;
            a[mi][0] = Ah[r * SA + ac];
            a[mi][1] = Ah[(r + 8) * SA + ac];
            a[mi][2] = Ah[r * SA + ac + 4];
            a[mi][3] = Ah[(r + 8) * SA + ac + 4];
        }
#pragma unroll
        for (int ni = 0; ni < 4; ni++) {
            int c = cbase + ni * 8 + gid;
            b[ni][0] = Bg[(size_t)c * 16 + bc];
            b[ni][1] = Bg[(size_t)c * 16 + bc + 4];
        }
#pragma unroll
        for (int mi = 0; mi < 2; mi++)
#pragma unroll
            for (int ni = 0; ni < 4; ni++)
                asm volatile(
                    "mma.sync.aligned.m16n8k16.row.col.f32.bf16.bf16.f32 "
                    "{%0,%1,%2,%3}, {%4,%5,%6,%7}, {%8,%9}, {%0,%1,%2,%3};"
                    : "+f"(acc[mi][ni][0]), "+f"(acc[mi][ni][1]),
                      "+f"(acc[mi][ni][2]), "+f"(acc[mi][ni][3])
                    : "r"(a[mi][0]), "r"(a[mi][1]), "r"(a[mi][2]), "r"(a[mi][3]),
                      "r"(b[ni][0]), "r"(b[ni][1]));
    }
}

// =============== the whole pipeline in ONE persistent kernel =======================
__global__ void __launch_bounds__(NTHR, 2) kern_all(const float* __restrict__ x0,
                                                    const float* __restrict__ x1,
                                                    float* __restrict__ out) {
    // pool: Ah[4608] | B 2x1280 | sq1s[512] | flags[64]  = 30.8 KB
    __shared__ uint32_t s_pool[7744];
    uint32_t* const Ah = s_pool;
    uint32_t* const Bbuf = s_pool + 4608;            // 2 x 1280
    float* const sq1s = (float*)(s_pool + 7168);     // 512 staged sq1_32
    int* const flags = (int*)(s_pool + 7680);        // [tile][warp] 8x8
    float* const sred = (float*)s_pool;              // phase-2 overlay

    const int tid  = threadIdx.x;
    const int bid  = blockIdx.x;
    const int lane = tid & 31;
    const int w    = tid >> 5;                // 0..7
    const int gid  = lane >> 2;
    const int pid  = lane & 3;
    const int wm   = w >> 1;                  // 0..3 (32-row strips)
    const int wn2  = w & 1;                   // 0..1 (32-col strips in 64)

    // =========== phase 0: fp32 -> bf16 (x1 split lo/hi), partial + full norms =====
    if (bid == 0) {
        if (tid == 0) g_cost = 0.0f;
        if (tid < ITERS) g_changed[tid] = 0;
    }
    {
        int g   = bid * NTHR + tid;           // 65536 = 8192 rows x 8 octs
        int row = g >> 3;
        int oct = g & 7;
        const float* src = (row < N) ? x0 + (size_t)row * D
                                     : x1 + (size_t)(row - N) * D;
        uint32_t* dsth;
        int base;
        if (row < N) { dsth = g_x0h + (size_t)row * 32; base = oct * 4; }
        else {
            int r1 = row - N;
            if (oct < 4) { dsth = g_x1l  + (size_t)r1 * 16; base = oct * 4; }
            else         { dsth = g_x1h2 + (size_t)r1 * 16; base = (oct - 4) * 4; }
        }
        float s = 0.0f;
#pragma unroll
        for (int i = 0; i < 2; i++) {
            float4 v4 = *(const float4*)(src + oct * 8 + i * 4);
            s += v4.x * v4.x + v4.y * v4.y + v4.z * v4.z + v4.w * v4.w;
            __nv_bfloat162 p0 = __floats2bfloat162_rn(v4.x, v4.y);
            __nv_bfloat162 p1 = __floats2bfloat162_rn(v4.z, v4.w);
            dsth[base + i * 2]     = *(uint32_t*)&p0;
            dsth[base + i * 2 + 1] = *(uint32_t*)&p1;
        }
        float s1 = s  + __shfl_xor_sync(0xffffffffu, s,  1);
        s1 += __shfl_xor_sync(0xffffffffu, s1, 2);
        float s2 = s1 + __shfl_xor_sync(0xffffffffu, s1, 4);
        if (oct == 0) {
            if (row < N) { g_sq0_32[row] = s1; g_sq0_64[row] = s2; }
            else         { g_sq1_32[row - N] = s1; g_sq1_64[row - N] = s2; }
        }
    }
    gsync();

    // =========== phase 1: 8 half-tiles (128x64) per block, 1 barrier/tile =========
    {
        const int rs  = bid >> 3;             // row slab 0..31
        const int cg8 = bid & 7;              // column group: cols cg8*512..+512
        const uint32_t sb = (uint32_t)__cvta_generic_to_shared(s_pool);

        // stage sq1_32 for this block's 512 columns
#pragma unroll
        for (int i = 0; i < 2; i++)
            sq1s[tid + i * NTHR] = g_sq1_32[cg8 * 512 + tid + i * NTHR];

        // A slab: 1024 uint4, 4/thread
        {
            const uint4* GA = (const uint4*)(g_x0h + (size_t)rs * 128 * 32);
#pragma unroll
            for (int i = 0; i < 4; i++) {
                int f = tid + i * NTHR; int r = f >> 3; int c4 = f & 7;
                cpa16(sb + (uint32_t)(r * SA + c4 * 4) * 4u, GA + r * 8 + c4);
            }
        }
        // B half-tile loader: 64 rows x 4 uint4 = 256, 1/thread
        auto loadB = [&](int buf, int h) {
            int r = tid >> 2; int c4 = tid & 3;
            int row = cg8 * 512 + h * 64 + r;
            cpa16(sb + 18432u + (uint32_t)buf * 5120u
                     + (uint32_t)(r * SBH + c4 * 4) * 4u,
                  (const uint4*)g_x1l + (size_t)row * 4 + c4);
        };
        loadB(0, 0);
        CP_COMMIT();

        // hoist sq0_32 for this warp's 32 rows
        const int gr = rs * 128 + wm * 32;
        float r032[2][2];
#pragma unroll
        for (int mi = 0; mi < 2; mi++) {
            r032[mi][0] = g_sq0_32[gr + mi * 16 + gid];
            r032[mi][1] = g_sq0_32[gr + mi * 16 + gid + 8];
        }

        const int AR = wm * 32, BR = wn2 * 32;
        int cur = 0;
        // -------- hot loop: ONE __syncthreads per tile, no flag exchange --------
        for (int h = 0; h < 8; h++) {
            CP_WAIT0();
            __syncthreads();   // B_h visible; all warps done with buffer cur^1
            if (h < 7) { loadB(cur ^ 1, h + 1); CP_COMMIT(); }

            float acc[2][4][4];
#pragma unroll
            for (int mi = 0; mi < 2; mi++)
#pragma unroll
                for (int ni = 0; ni < 4; ni++)
#pragma unroll
                    for (int f = 0; f < 4; f++) acc[mi][ni][f] = 0.0f;

            mma_lo_s(acc, Ah, Bbuf + cur * 1280, AR, BR, gid, pid);

            // exact screen: partial M (dims 0..31) lower-bounds full M
            const int lc0 = h * 64 + wn2 * 32;
            int need = 0;
#pragma unroll
            for (int mi = 0; mi < 2; mi++)
#pragma unroll
                for (int ni = 0; ni < 4; ni++) {
                    int c = lc0 + ni * 8 + 2 * pid;
                    float s1a = sq1s[c], s1b = sq1s[c + 1];
                    float m0 = fmaf(-2.0f, acc[mi][ni][0], r032[mi][0] + s1a);
                    float m1 = fmaf(-2.0f, acc[mi][ni][1], r032[mi][0] + s1b);
                    float m2 = fmaf(-2.0f, acc[mi][ni][2], r032[mi][1] + s1a);
                    float m3 = fmaf(-2.0f, acc[mi][ni][3], r032[mi][1] + s1b);
                    need |= (fminf(fminf(m0, m1), fminf(m2, m3)) < 11.0f) ? 1 : 0;
                }
            // warp-uniform collective FIRST, then the divergent store
            int anyb = __ballot_sync(0xffffffffu, need) ? 1 : 0;
            if (lane == 0) flags[h * 8 + w] = anyb;
            cur ^= 1;
        }
        __syncthreads();       // all flags visible

        // -------- cold pass: complete flagged half-tiles exactly ---------------
        int blkany = 0;
        for (int h = 0; h < 8; h++) {
            int f = flags[h * 8 + 0] | flags[h * 8 + 1] | flags[h * 8 + 2] |
                    flags[h * 8 + 3] | flags[h * 8 + 4] | flags[h * 8 + 5] |
                    flags[h * 8 + 6] | flags[h * 8 + 7];
            if (tid == 0) g_map2[rs * NHT + cg8 * 8 + h] = f;
            blkany |= f;
            if (!f) continue;

            const int gc = cg8 * 512 + h * 64 + wn2 * 32;
            float acc[2][4][4];
#pragma unroll
            for (int mi = 0; mi < 2; mi++)
#pragma unroll
                for (int ni = 0; ni < 4; ni++)
#pragma unroll
                    for (int ff = 0; ff < 4; ff++) acc[mi][ni][ff] = 0.0f;
            mma_full_g(acc, Ah, gc, AR, gid, pid);   // dims 0..63, B from global

#pragma unroll
            for (int mi = 0; mi < 2; mi++) {
                float s0a = g_sq0_64[gr + mi * 16 + gid];
                float s0b = g_sq0_64[gr + mi * 16 + gid + 8];
#pragma unroll
                for (int ni = 0; ni < 4; ni++) {
                    int c = gc + ni * 8 + 2 * pid;
                    float s1a = g_sq1_64[c], s1b = g_sq1_64[c + 1];
                    float m0 = fmaxf(fmaf(-2.0f, acc[mi][ni][0], s0a + s1a), 0.0f);
                    float m1 = fmaxf(fmaf(-2.0f, acc[mi][ni][1], s0a + s1b), 0.0f);
                    float m2 = fmaxf(fmaf(-2.0f, acc[mi][ni][2], s0b + s1a), 0.0f);
                    float m3 = fmaxf(fmaf(-2.0f, acc[mi][ni][3], s0b + s1b), 0.0f);
                    int r0 = gr + mi * 16 + gid;
                    *(float2*)(g_M + (size_t)r0 * N + c)       = make_float2(m0, m1);
                    *(float2*)(g_M + (size_t)(r0 + 8) * N + c) = make_float2(m2, m3);
                    *(float2*)(g_K + (size_t)r0 * N + c)       =
                        make_float2(expf(-10.0f * m0), expf(-10.0f * m1));
                    *(float2*)(g_K + (size_t)(r0 + 8) * N + c) =
                        make_float2(expf(-10.0f * m2), expf(-10.0f * m3));
                }
            }
        }
        if (tid == 0) g_blockany[bid] = blkany;
    }
    gsync();

    // =========== phase 2: Sinkhorn (or exact zero fast path) ======================
    {
        int loc = g_blockany[tid];            // NTHR == NB
        if (!__syncthreads_or(loc)) {
            if (bid == 0 && tid == 0) out[0] = 0.0f;   // P == 0 exactly
            return;                                     // uniform across blocks
        }
    }

    const float AB    = 1.0f / (float)N;
    const float DELTA = 1e-8f;
    {
        int gi = bid * NTHR + tid;
        if (gi < N) { g_u[gi] = 1.0f; g_v[gi] = 1.0f; }
    }
    gsync();

    for (int it = 0; it < ITERS; it++) {
        // u-pass: 16 rows/block, 2 rows/warp; skip all-zero half-tiles
#pragma unroll
        for (int rr = 0; rr < 2; rr++) {
            int r  = bid * 16 + w * 2 + rr;
            int rt = r >> 7;
            const int* map = g_map2 + rt * NHT;
            const float4* kr = (const float4*)(g_K + (size_t)r * N);
            const float4* vv = (const float4*)g_v;
            float s = 0.0f;
            for (int hct = 0; hct < NHT; hct++) {
                if (!map[hct]) continue;
                if (lane < 16) {
                    int j = hct * 16 + lane;
                    float4 kq = kr[j];
                    float4 vq = vv[j];
                    s += kq.x * vq.x + kq.y * vq.y + kq.z * vq.z + kq.w * vq.w;
                }
            }
#pragma unroll
            for (int o = 16; o; o >>= 1) s += __shfl_xor_sync(0xffffffffu, s, o);
            if (lane == 0) {
                float un = AB / (s + DELTA);
                if (un != g_u[r]) g_changed[it] = 1;
                g_u[r] = un;
            }
        }
        gsync();

        // v-pass: 16 cols/block; col = bid*16 + (tid>>4), 16-row stride
        {
            int cl  = tid >> 4;               // 0..15
            int ri  = tid & 15;
            int c   = bid * 16 + cl;
            int hct = bid >> 2;               // 16-col stripe lies in this half-tile
            float s = 0.0f;
            for (int rt = 0; rt < NT; rt++) {
                if (!g_map2[rt * NHT + hct]) continue;
                int rbase = rt * 128;
#pragma unroll 8
                for (int r = rbase + ri; r < rbase + 128; r += 16)
                    s += g_K[(size_t)r * N + c] * g_u[r];
            }
            sred[tid] = s;
            __syncthreads();
            if (tid < 16) {
                float t = 0.0f;
#pragma unroll
                for (int g = 0; g < 16; g++) t += sred[tid * 16 + g];
                float vn = AB / (t + DELTA);
                int c2 = bid * 16 + tid;
                if (vn != g_v[c2]) g_changed[it] = 1;
                g_v[c2] = vn;
            }
        }
        gsync();

        if (g_changed[it] == 0) break;        // exact bitwise fixed point
    }

    // cost = sum_ij u_i * K_ij * v_j * M_ij (zero half-tiles contribute 0)
    {
        float wsum = 0.0f;
#pragma unroll
        for (int rr = 0; rr < 2; rr++) {
            int r  = bid * 16 + w * 2 + rr;
            int rt = r >> 7;
            const int* map = g_map2 + rt * NHT;
            const float4* kr = (const float4*)(g_K + (size_t)r * N);
            const float4* mr = (const float4*)(g_M + (size_t)r * N);
            const float4* vv = (const float4*)g_v;
            float s = 0.0f;
            for (int hct = 0; hct < NHT; hct++) {
                if (!map[hct]) continue;
                if (lane < 16) {
                    int j = hct * 16 + lane;
                    float4 kq = kr[j];
                    float4 mq = mr[j];
                    float4 vq = vv[j];
                    s += kq.x * mq.x * vq.x + kq.y * mq.y * vq.y
                       + kq.z * mq.z * vq.z + kq.w * mq.w * vq.w;
                }
            }
#pragma unroll
            for (int o = 16; o; o >>= 1) s += __shfl_xor_sync(0xffffffffu, s, o);
            if (lane == 0) wsum += s * g_u[r];
        }
        if (lane == 0) atomicAdd(&g_cost, wsum);
    }
    gsync();
    if (bid == 0 && tid == 0) out[0] = g_cost;
}

// ---------------- launch: ONE kernel ----------------------------------------------
extern "C" void kernel_launch(void* const* d_in, const int* in_sizes, int n_in,
                              void* d_out, int out_size) {
    const float* x0 = (const float*)d_in[0];
    const float* x1 = (const float*)d_in[1];
    float* out = (float*)d_out;
    kern_all<<<NB, NTHR>>>(x0, x1, out);
}